// round 11
// baseline (speedup 1.0000x reference)
#include <cuda_runtime.h>

#define NN 2048
#define FEAT 64
#define HID 16
#define C 8
#define NG 64
#define MAXSEG 128     // hard bound: sum ceil(len_g/32) <= 64 + 64
#define NB 148         // persistent blocks; one per SM, all resident in wave 1

// scratch (allocation-free rule: device globals; zero-init at load, barrier
// counters are restored to 0 by the last block of every call -> stateless)
__device__ __align__(16) float g_node[NN * C];
__device__ __align__(16) float e_tab[11 * C];
__device__ int d_seg_start[MAXSEG];
__device__ int d_seg_len[MAXSEG];
__device__ int d_seg_graph[MAXSEG];
__device__ int d_nseg;
__device__ int d_bar0;
__device__ int d_bar1;

// ---------------------------------------------------------------------------
// Fused kernel, 148 blocks x 256 threads, ONE launch.
// Phase A (blocks 0..63): g_node via transposed MLP (warp-uniform weights,
//   smem x tile). Block 0: e-table, d_out zeroing, parallel segment build.
// Global spin barrier (all 148 blocks resident by construction).
// Phase B (all blocks): k2 histogram-contraction tasks, strided by blockIdx.
// ---------------------------------------------------------------------------
__global__ void __launch_bounds__(256) tgnan_fused(
    const float* __restrict__ x,
    const int*   __restrict__ batch,
    const float* __restrict__ w1, const float* __restrict__ b1,
    const float* __restrict__ w2, const float* __restrict__ b2,
    const float* __restrict__ rw1, const float* __restrict__ rb1,
    const float* __restrict__ rw2, const float* __restrict__ rb2,
    const float* __restrict__ dist,
    float* __restrict__ out)
{
    __shared__ float x_s[32 * 65];            // phase A: 32 nodes x 64 feats, pad
    __shared__ float ps[8][32][C];            // phase A: per-warp partials
    __shared__ float er_s[11][C];             // phase B: e-table
    __shared__ float bp[8][C];                // phase B: per-warp partials

    const int tid  = threadIdx.x;
    const int wid  = tid >> 5;
    const int lane = tid & 31;

    // ======================= Phase A =======================
    if (blockIdx.x < 64) {
        const int n0 = blockIdx.x * 32;
        for (int i = tid; i < 32 * 64; i += 256) {
            const int r = i >> 6, cc = i & 63;
            x_s[r * 65 + cc] = __ldg(x + (size_t)(n0 + r) * FEAT + cc);
        }
        __syncthreads();

        float acc[C];
#pragma unroll
        for (int c = 0; c < C; c++) acc[c] = 0.0f;

#pragma unroll
        for (int k = 0; k < 8; k++) {
            const int f = wid * 8 + k;            // warp-uniform feature
            const float xv = x_s[lane * 65 + f];  // conflict-free
            const float4* b2p = reinterpret_cast<const float4*>(b2 + f * C);
            const float4 b2a = __ldg(b2p);
            const float4 b2b = __ldg(b2p + 1);
            acc[0] += b2a.x; acc[1] += b2a.y; acc[2] += b2a.z; acc[3] += b2a.w;
            acc[4] += b2b.x; acc[5] += b2b.y; acc[6] += b2b.z; acc[7] += b2b.w;
#pragma unroll
            for (int h = 0; h < HID; h++) {
                const float hv = fmaxf(fmaf(xv, __ldg(w1 + f * HID + h),
                                            __ldg(b1 + f * HID + h)), 0.0f);
                const float4* wp = reinterpret_cast<const float4*>(w2 + (size_t)(f * HID + h) * C);
                const float4 wa = __ldg(wp);      // warp-uniform 32B
                const float4 wb = __ldg(wp + 1);
                acc[0] = fmaf(hv, wa.x, acc[0]);
                acc[1] = fmaf(hv, wa.y, acc[1]);
                acc[2] = fmaf(hv, wa.z, acc[2]);
                acc[3] = fmaf(hv, wa.w, acc[3]);
                acc[4] = fmaf(hv, wb.x, acc[4]);
                acc[5] = fmaf(hv, wb.y, acc[5]);
                acc[6] = fmaf(hv, wb.z, acc[6]);
                acc[7] = fmaf(hv, wb.w, acc[7]);
            }
        }
#pragma unroll
        for (int c = 0; c < C; c++) ps[wid][lane][c] = acc[c];
        __syncthreads();
        {
            const int n = tid >> 3, c = tid & 7;
            float s = 0.0f;
#pragma unroll
            for (int ww = 0; ww < 8; ww++) s += ps[ww][n][c];
            g_node[(size_t)(n0 + n) * C + c] = s;  // coalesced
        }
    }

    if (blockIdx.x == 0) {
        // e-table: rho MLP at dist = 0..10 (dist = -1 contributes 0)
        if (tid < 11) {
            const float dd = (float)tid;
            float a2[C];
#pragma unroll
            for (int c = 0; c < C; c++) a2[c] = rb2[c];
#pragma unroll
            for (int h = 0; h < HID; h++) {
                const float hv = fmaxf(fmaf(dd, rw1[h], rb1[h]), 0.0f);
#pragma unroll
                for (int c = 0; c < C; c++)
                    a2[c] = fmaf(hv, rw2[h * C + c], a2[c]);
            }
#pragma unroll
            for (int c = 0; c < C; c++) e_tab[tid * C + c] = a2[c];
        }
        // zero output (d_out is poisoned; phase B accumulates atomically)
        for (int i = tid; i < NG * C; i += 256) out[i] = 0.0f;

        // parallel segment build (order-independent slot allocation)
        __shared__ int bstart[NG + 1];
        __shared__ int nseg_s;
        if (tid <= NG) bstart[tid] = (tid == NG) ? NN : -1;
        if (tid == 0) nseg_s = 0;
        __syncthreads();
        if (tid < 64) {
            const int r0 = tid * 32;
            int prev = (r0 == 0) ? -1 : __ldg(batch + r0 - 1);
            for (int i = 0; i < 32; i++) {
                const int b = __ldg(batch + r0 + i);
                if (b != prev) bstart[b] = r0 + i;   // unique writer per graph
                prev = b;
            }
        }
        __syncthreads();
        if (tid < NG) {
            const int s = bstart[tid];
            if (s >= 0) {
                int e = NN;
                for (int g2 = tid + 1; g2 <= NG; g2++) {
                    if (bstart[g2] >= 0) { e = bstart[g2]; break; }
                }
                const int len = e - s;
                const int ns  = (len + 31) >> 5;
                const int off = atomicAdd(&nseg_s, ns);
                for (int i = 0; i < ns; i++) {
                    d_seg_start[off + i] = s + i * 32;
                    d_seg_len[off + i]   = min(32, len - i * 32);
                    d_seg_graph[off + i] = tid;
                }
            }
        }
        __syncthreads();
        if (tid == 0) d_nseg = nseg_s;
    }

    // ======================= global barrier =======================
    __syncthreads();
    if (tid == 0) {
        __threadfence();                      // publish phase-A writes
        atomicAdd(&d_bar0, 1);
        while (*(volatile int*)&d_bar0 < NB) {}
    }
    __syncthreads();
    __threadfence();                          // acquire phase-A writes

    // ======================= Phase B =======================
    if (tid < 11 * C) ((float*)er_s)[tid] = e_tab[tid];
    __syncthreads();

    const int ntask = d_nseg * 8;             // 8 m-groups x nseg segments
    for (int task = blockIdx.x; task < ntask; task += NB) {
        const int mg  = task & 7;
        const int seg = task >> 3;
        const int m     = (mg * 8 + wid) * 32 + lane;
        const int start = d_seg_start[seg];
        const int len   = d_seg_len[seg];
        const int gb    = d_seg_graph[seg];

        const float* pd = dist + (size_t)start * NN + m;

        unsigned long long h0 = 0ull, h1 = 0ull; // 12 buckets x 10-bit fields
#pragma unroll
        for (int half = 0; half < 2; half++) {
            float fd[16];
#pragma unroll
            for (int i = 0; i < 16; i++) {       // 16 independent predicated LDGs
                const int r = half * 16 + i;
                fd[i] = (r < len) ? __ldg(pd + (size_t)r * NN) : -1.0f;
            }
#pragma unroll
            for (int i = 0; i < 16; i++) {
                int di = (int)fd[i] + 1;         // -1..10 -> 0..11 (exact ints)
                di = max(0, min(11, di));
                const bool hi = di >= 6;
                const unsigned long long inc = 1ull << (10 * (hi ? di - 6 : di));
                if (hi) h1 += inc; else h0 += inc;
            }
        }

        float p[C];
#pragma unroll
        for (int c = 0; c < C; c++) p[c] = 0.0f;
#pragma unroll
        for (int d = 1; d < 12; d++) {           // bucket 0 (dist=-1) -> 0
            const unsigned int cnt = (unsigned int)
                ((d < 6 ? (h0 >> (10 * d)) : (h1 >> (10 * (d - 6)))) & 1023u);
            const float fc = (float)cnt;
#pragma unroll
            for (int c = 0; c < C; c++)
                p[c] = fmaf(fc, er_s[d - 1][c], p[c]);
        }
        {
            const float4* gp = reinterpret_cast<const float4*>(g_node + (size_t)m * C);
            const float4 ga = gp[0];
            const float4 gb4 = gp[1];
            p[0] *= ga.x;  p[1] *= ga.y;  p[2] *= ga.z;  p[3] *= ga.w;
            p[4] *= gb4.x; p[5] *= gb4.y; p[6] *= gb4.z; p[7] *= gb4.w;
        }
#pragma unroll
        for (int off = 16; off; off >>= 1)
#pragma unroll
            for (int c = 0; c < C; c++)
                p[c] += __shfl_xor_sync(0xffffffffu, p[c], off);

        if (lane == 0) {
#pragma unroll
            for (int c = 0; c < C; c++) bp[wid][c] = p[c];
        }
        __syncthreads();
        if (tid < C) {
            float s = 0.0f;
#pragma unroll
            for (int ww = 0; ww < 8; ww++) s += bp[ww][tid];
            atomicAdd(out + gb * C + tid, s);
        }
        __syncthreads();                      // bp reused next iteration
    }

    // ======================= stateless reset =======================
    __syncthreads();
    if (tid == 0) {
        const int o = atomicAdd(&d_bar1, 1);
        if (o == NB - 1) {                    // last block restores zeros
            d_bar1 = 0;
            __threadfence();
            d_bar0 = 0;
        }
    }
}

// ---------------------------------------------------------------------------
extern "C" void kernel_launch(void* const* d_in, const int* in_sizes, int n_in,
                              void* d_out, int out_size)
{
    const float* x    = (const float*)d_in[0];
    const float* dist = (const float*)d_in[1];
    const int*   bv   = (const int*)d_in[2];
    const float* fw1  = (const float*)d_in[3];
    const float* fb1  = (const float*)d_in[4];
    const float* fw2  = (const float*)d_in[5];
    const float* fb2  = (const float*)d_in[6];
    const float* rw1  = (const float*)d_in[7];
    const float* rb1  = (const float*)d_in[8];
    const float* rw2  = (const float*)d_in[9];
    const float* rb2  = (const float*)d_in[10];
    float* out = (float*)d_out;

    tgnan_fused<<<NB, 256>>>(x, bv, fw1, fb1, fw2, fb2, rw1, rb1, rw2, rb2,
                             dist, out);
}

// round 13
// speedup vs baseline: 1.5000x; 1.5000x over previous
#include <cuda_runtime.h>

#define NN 2048
#define FEAT 64
#define HID 16
#define C 8
#define NG 64
#define MAXSEG 128     // hard bound: sum ceil(len_g/32) <= 64 + 64
#define NB 592         // persistent blocks; 4 per SM, all resident in wave 1

// scratch (allocation-free rule: device globals; zero-init at load, barrier
// counters are restored to 0 by the last block of every call -> stateless)
__device__ __align__(16) float g_node[NN * C];
__device__ __align__(16) float e_tab[11 * C];
__device__ int d_seg_start[MAXSEG];
__device__ int d_seg_len[MAXSEG];
__device__ int d_seg_graph[MAXSEG];
__device__ int d_nseg;
__device__ int d_bar0;
__device__ int d_bar1;

// ---------------------------------------------------------------------------
// Fused kernel, 592 blocks x 256 threads, ONE launch, all blocks co-resident
// (44 regs, ~17KB smem -> 4 blocks/SM). Phase A (blocks 0..127): g_node via
// transposed MLP, 16 nodes/block. Block 0: e-table, out zeroing, segment
// build. Global spin barrier. Phase B (all blocks): histogram contraction.
// ---------------------------------------------------------------------------
__global__ void __launch_bounds__(256) tgnan_fused(
    const float* __restrict__ x,
    const int*   __restrict__ batch,
    const float* __restrict__ w1, const float* __restrict__ b1,
    const float* __restrict__ w2, const float* __restrict__ b2,
    const float* __restrict__ rw1, const float* __restrict__ rb1,
    const float* __restrict__ rw2, const float* __restrict__ rb2,
    const float* __restrict__ dist,
    float* __restrict__ out)
{
    __shared__ float x_s[16 * 65];            // phase A: 16 nodes x 64 feats, pad
    __shared__ float ps[16][16][C];           // phase A: [slot][node][c] partials
    __shared__ float er_s[11][C];             // phase B: e-table
    __shared__ float bp[8][C];                // phase B: per-warp partials

    const int tid  = threadIdx.x;
    const int wid  = tid >> 5;
    const int lane = tid & 31;

    // ======================= Phase A =======================
    if (blockIdx.x < 128) {
        const int n0 = blockIdx.x * 16;
        for (int i = tid; i < 16 * 64; i += 256) {
            const int r = i >> 6, cc = i & 63;
            x_s[r * 65 + cc] = __ldg(x + (size_t)(n0 + r) * FEAT + cc);
        }
        __syncthreads();

        // thread = (slot, node): slot = tid>>4 (0..15), node = tid&15.
        // slot handles features f = slot*4 .. slot*4+3 (4 features each).
        const int slot = tid >> 4;
        const int node = tid & 15;
        float acc[C];
#pragma unroll
        for (int c = 0; c < C; c++) acc[c] = 0.0f;

#pragma unroll
        for (int k = 0; k < 4; k++) {
            const int f = slot * 4 + k;
            const float xv = x_s[node * 65 + f];
            const float4* b2p = reinterpret_cast<const float4*>(b2 + f * C);
            const float4 b2a = __ldg(b2p);
            const float4 b2b = __ldg(b2p + 1);
            acc[0] += b2a.x; acc[1] += b2a.y; acc[2] += b2a.z; acc[3] += b2a.w;
            acc[4] += b2b.x; acc[5] += b2b.y; acc[6] += b2b.z; acc[7] += b2b.w;
#pragma unroll
            for (int h = 0; h < HID; h++) {
                const float hv = fmaxf(fmaf(xv, __ldg(w1 + f * HID + h),
                                            __ldg(b1 + f * HID + h)), 0.0f);
                const float4* wp = reinterpret_cast<const float4*>(w2 + (size_t)(f * HID + h) * C);
                const float4 wa = __ldg(wp);
                const float4 wb = __ldg(wp + 1);
                acc[0] = fmaf(hv, wa.x, acc[0]);
                acc[1] = fmaf(hv, wa.y, acc[1]);
                acc[2] = fmaf(hv, wa.z, acc[2]);
                acc[3] = fmaf(hv, wa.w, acc[3]);
                acc[4] = fmaf(hv, wb.x, acc[4]);
                acc[5] = fmaf(hv, wb.y, acc[5]);
                acc[6] = fmaf(hv, wb.z, acc[6]);
                acc[7] = fmaf(hv, wb.w, acc[7]);
            }
        }
#pragma unroll
        for (int c = 0; c < C; c++) ps[slot][node][c] = acc[c];
        __syncthreads();
        // final: 128 threads, one (node, channel) each; sum 16 slots
        if (tid < 128) {
            const int n = tid >> 3, c = tid & 7;
            float s = 0.0f;
#pragma unroll
            for (int ss = 0; ss < 16; ss++) s += ps[ss][n][c];
            g_node[(size_t)(n0 + n) * C + c] = s;  // coalesced
        }
    }

    if (blockIdx.x == 0) {
        // e-table: rho MLP at dist = 0..10 (dist = -1 contributes 0)
        if (tid < 11) {
            const float dd = (float)tid;
            float a2[C];
#pragma unroll
            for (int c = 0; c < C; c++) a2[c] = rb2[c];
#pragma unroll
            for (int h = 0; h < HID; h++) {
                const float hv = fmaxf(fmaf(dd, rw1[h], rb1[h]), 0.0f);
#pragma unroll
                for (int c = 0; c < C; c++)
                    a2[c] = fmaf(hv, rw2[h * C + c], a2[c]);
            }
#pragma unroll
            for (int c = 0; c < C; c++) e_tab[tid * C + c] = a2[c];
        }
        // zero output (d_out is poisoned; phase B accumulates atomically)
        for (int i = tid; i < NG * C; i += 256) out[i] = 0.0f;

        // parallel segment build (order-independent slot allocation)
        __shared__ int bstart[NG + 1];
        __shared__ int nseg_s;
        if (tid <= NG) bstart[tid] = (tid == NG) ? NN : -1;
        if (tid == 0) nseg_s = 0;
        __syncthreads();
        if (tid < 64) {
            const int r0 = tid * 32;
            int prev = (r0 == 0) ? -1 : __ldg(batch + r0 - 1);
            for (int i = 0; i < 32; i++) {
                const int b = __ldg(batch + r0 + i);
                if (b != prev) bstart[b] = r0 + i;   // unique writer per graph
                prev = b;
            }
        }
        __syncthreads();
        if (tid < NG) {
            const int s = bstart[tid];
            if (s >= 0) {
                int e = NN;
                for (int g2 = tid + 1; g2 <= NG; g2++) {
                    if (bstart[g2] >= 0) { e = bstart[g2]; break; }
                }
                const int len = e - s;
                const int ns  = (len + 31) >> 5;
                const int off = atomicAdd(&nseg_s, ns);
                for (int i = 0; i < ns; i++) {
                    d_seg_start[off + i] = s + i * 32;
                    d_seg_len[off + i]   = min(32, len - i * 32);
                    d_seg_graph[off + i] = tid;
                }
            }
        }
        __syncthreads();
        if (tid == 0) d_nseg = nseg_s;
    }

    // ======================= global barrier =======================
    __syncthreads();
    if (tid == 0) {
        __threadfence();                      // publish phase-A writes
        atomicAdd(&d_bar0, 1);
        while (*(volatile int*)&d_bar0 < NB) { __nanosleep(64); }
    }
    __syncthreads();
    __threadfence();                          // acquire phase-A writes

    // ======================= Phase B =======================
    if (tid < 11 * C) ((float*)er_s)[tid] = e_tab[tid];
    __syncthreads();

    const int ntask = d_nseg * 8;             // 8 m-groups x nseg segments
    for (int task = blockIdx.x; task < ntask; task += NB) {
        const int mg  = task & 7;
        const int seg = task >> 3;
        const int m     = (mg * 8 + wid) * 32 + lane;
        const int start = d_seg_start[seg];
        const int len   = d_seg_len[seg];
        const int gb    = d_seg_graph[seg];

        const float* pd = dist + (size_t)start * NN + m;

        unsigned long long h0 = 0ull, h1 = 0ull; // 12 buckets x 10-bit fields
#pragma unroll
        for (int half = 0; half < 2; half++) {
            float fd[16];
#pragma unroll
            for (int i = 0; i < 16; i++) {       // 16 independent predicated LDGs
                const int r = half * 16 + i;
                fd[i] = (r < len) ? __ldg(pd + (size_t)r * NN) : -1.0f;
            }
#pragma unroll
            for (int i = 0; i < 16; i++) {
                int di = (int)fd[i] + 1;         // -1..10 -> 0..11 (exact ints)
                di = max(0, min(11, di));
                const bool hi = di >= 6;
                const unsigned long long inc = 1ull << (10 * (hi ? di - 6 : di));
                if (hi) h1 += inc; else h0 += inc;
            }
        }

        float p[C];
#pragma unroll
        for (int c = 0; c < C; c++) p[c] = 0.0f;
#pragma unroll
        for (int d = 1; d < 12; d++) {           // bucket 0 (dist=-1) -> 0
            const unsigned int cnt = (unsigned int)
                ((d < 6 ? (h0 >> (10 * d)) : (h1 >> (10 * (d - 6)))) & 1023u);
            const float fc = (float)cnt;
#pragma unroll
            for (int c = 0; c < C; c++)
                p[c] = fmaf(fc, er_s[d - 1][c], p[c]);
        }
        {
            const float4* gp = reinterpret_cast<const float4*>(g_node + (size_t)m * C);
            const float4 ga = gp[0];
            const float4 gb4 = gp[1];
            p[0] *= ga.x;  p[1] *= ga.y;  p[2] *= ga.z;  p[3] *= ga.w;
            p[4] *= gb4.x; p[5] *= gb4.y; p[6] *= gb4.z; p[7] *= gb4.w;
        }
#pragma unroll
        for (int off = 16; off; off >>= 1)
#pragma unroll
            for (int c = 0; c < C; c++)
                p[c] += __shfl_xor_sync(0xffffffffu, p[c], off);

        if (lane == 0) {
#pragma unroll
            for (int c = 0; c < C; c++) bp[wid][c] = p[c];
        }
        __syncthreads();
        if (tid < C) {
            float s = 0.0f;
#pragma unroll
            for (int ww = 0; ww < 8; ww++) s += bp[ww][tid];
            atomicAdd(out + gb * C + tid, s);
        }
        __syncthreads();                      // bp reused next iteration
    }

    // ======================= stateless reset =======================
    if (tid == 0) {
        const int o = atomicAdd(&d_bar1, 1);
        if (o == NB - 1) {                    // last block restores zeros
            d_bar1 = 0;
            __threadfence();
            d_bar0 = 0;
        }
    }
}

// ---------------------------------------------------------------------------
extern "C" void kernel_launch(void* const* d_in, const int* in_sizes, int n_in,
                              void* d_out, int out_size)
{
    const float* x    = (const float*)d_in[0];
    const float* dist = (const float*)d_in[1];
    const int*   bv   = (const int*)d_in[2];
    const float* fw1  = (const float*)d_in[3];
    const float* fb1  = (const float*)d_in[4];
    const float* fw2  = (const float*)d_in[5];
    const float* fb2  = (const float*)d_in[6];
    const float* rw1  = (const float*)d_in[7];
    const float* rb1  = (const float*)d_in[8];
    const float* rw2  = (const float*)d_in[9];
    const float* rb2  = (const float*)d_in[10];
    float* out = (float*)d_out;

    tgnan_fused<<<NB, 256>>>(x, bv, fw1, fb1, fw2, fb2, rw1, rb1, rw2, rb2,
                             dist, out);
}

// round 14
// speedup vs baseline: 2.2649x; 1.5099x over previous
#include <cuda_runtime.h>

#define NN 2048
#define FEAT 64
#define HID 16
#define C 8
#define NG 64
#define MAXSEG 128     // hard bound: sum ceil(len_g/32) <= 64 + 64
#define NB 592         // persistent blocks; 4/SM, all wave-1 resident
#define NA 128         // phase-A blocks (g_node)
#define NBB (NB - NA)  // 464 histogram blocks
#define MAXRND 3       // ceil(MAXSEG*8 / NBB) = ceil(1024/464) = 3

// device globals (allocation-free rule); barrier counters restored to 0 by
// the last block of every call -> kernel is stateless/graph-replayable.
__device__ __align__(16) float g_node[NN * C];
__device__ int d_bar0;
__device__ int d_bar1;

// ---------------------------------------------------------------------------
// Single fused persistent kernel, 592 x 256, one launch.
//  * every block: local e-table + local segment table (parallel scan, L2-hot)
//  * blocks 0..127: phase A (g_node MLP); block 0 zeroes out
//  * blocks 128..591: histogram tasks IMMEDIATELY (dist pass needs no phase-A
//    data) -> held in registers. Overlaps with phase A.
//  * global barrier (g_node ready) -> emit held histograms -> reset.
// ---------------------------------------------------------------------------
__global__ void __launch_bounds__(256, 4) tgnan_fused(
    const float* __restrict__ x,
    const int*   __restrict__ batch,
    const float* __restrict__ w1, const float* __restrict__ b1,
    const float* __restrict__ w2, const float* __restrict__ b2,
    const float* __restrict__ rw1, const float* __restrict__ rb1,
    const float* __restrict__ rw2, const float* __restrict__ rb2,
    const float* __restrict__ dist,
    float* __restrict__ out)
{
    __shared__ float x_s[16 * 65];
    __shared__ float ps[16][16][C];
    __shared__ float er_s[11][C];
    __shared__ float bp[8][C];
    __shared__ int bstart[NG + 1];
    __shared__ int s_start[MAXSEG], s_len[MAXSEG], s_graph[MAXSEG];
    __shared__ int nseg_s, w0sum;

    const int tid  = threadIdx.x;
    const int wid  = tid >> 5;
    const int lane = tid & 31;
    const int bx   = blockIdx.x;

    // ---- local e-table: rho MLP at dist = 0..10 (dist=-1 contributes 0) ----
    if (tid < 11) {
        const float dd = (float)tid;
        float a2[C];
#pragma unroll
        for (int c = 0; c < C; c++) a2[c] = rb2[c];
#pragma unroll
        for (int h = 0; h < HID; h++) {
            const float hv = fmaxf(fmaf(dd, rw1[h], rb1[h]), 0.0f);
#pragma unroll
            for (int c = 0; c < C; c++)
                a2[c] = fmaf(hv, rw2[h * C + c], a2[c]);
        }
#pragma unroll
        for (int c = 0; c < C; c++) er_s[tid][c] = a2[c];
    }

    // ---- local segment table: parallel boundary scan (L2-hot batch) ----
    if (tid <= NG) bstart[tid] = (tid == NG) ? NN : -1;
    __syncthreads();
#pragma unroll
    for (int r = tid; r < NN; r += 256) {
        const int b    = __ldg(batch + r);
        const int prev = (r == 0) ? -1 : __ldg(batch + r - 1);
        if (b != prev) bstart[b] = r;          // unique writer per graph
    }
    __syncthreads();
    {
        int ns = 0, len0 = 0, s0 = -1;
        if (tid < NG) {
            s0 = bstart[tid];
            if (s0 >= 0) {
                int e = NN;
                for (int g2 = tid + 1; g2 <= NG; g2++)
                    if (bstart[g2] >= 0) { e = bstart[g2]; break; }
                len0 = e - s0;
                ns = (len0 + 31) >> 5;
            }
        }
        // deterministic prefix over 64 graph-threads (warps 0 and 1)
        int v = ns;
#pragma unroll
        for (int o = 1; o < 32; o <<= 1) {
            const int t2 = __shfl_up_sync(0xffffffffu, v, o);
            if (lane >= o) v += t2;
        }
        if (tid == 31) w0sum = v;
        __syncthreads();
        if (tid < NG) {
            const int off = v - ns + ((tid >= 32) ? w0sum : 0);
            for (int i = 0; i < ns; i++) {
                s_start[off + i] = s0 + i * 32;
                s_len[off + i]   = min(32, len0 - i * 32);
                s_graph[off + i] = tid;
            }
            if (tid == NG - 1) nseg_s = off + ns;
        }
    }
    __syncthreads();

    // ======================= Phase A (blocks 0..127) =======================
    if (bx < NA) {
        const int n0 = bx * 16;
        for (int i = tid; i < 16 * 64; i += 256) {
            const int r = i >> 6, cc = i & 63;
            x_s[r * 65 + cc] = __ldg(x + (size_t)(n0 + r) * FEAT + cc);
        }
        __syncthreads();

        const int slot = tid >> 4;            // 0..15: features slot*4..slot*4+3
        const int node = tid & 15;
        float acc[C];
#pragma unroll
        for (int c = 0; c < C; c++) acc[c] = 0.0f;
#pragma unroll
        for (int k = 0; k < 4; k++) {
            const int f = slot * 4 + k;
            const float xv = x_s[node * 65 + f];
            const float4* b2p = reinterpret_cast<const float4*>(b2 + f * C);
            const float4 b2a = __ldg(b2p);
            const float4 b2b = __ldg(b2p + 1);
            acc[0] += b2a.x; acc[1] += b2a.y; acc[2] += b2a.z; acc[3] += b2a.w;
            acc[4] += b2b.x; acc[5] += b2b.y; acc[6] += b2b.z; acc[7] += b2b.w;
#pragma unroll
            for (int h = 0; h < HID; h++) {
                const float hv = fmaxf(fmaf(xv, __ldg(w1 + f * HID + h),
                                            __ldg(b1 + f * HID + h)), 0.0f);
                const float4* wp = reinterpret_cast<const float4*>(w2 + (size_t)(f * HID + h) * C);
                const float4 wa = __ldg(wp);
                const float4 wb = __ldg(wp + 1);
                acc[0] = fmaf(hv, wa.x, acc[0]);
                acc[1] = fmaf(hv, wa.y, acc[1]);
                acc[2] = fmaf(hv, wa.z, acc[2]);
                acc[3] = fmaf(hv, wa.w, acc[3]);
                acc[4] = fmaf(hv, wb.x, acc[4]);
                acc[5] = fmaf(hv, wb.y, acc[5]);
                acc[6] = fmaf(hv, wb.z, acc[6]);
                acc[7] = fmaf(hv, wb.w, acc[7]);
            }
        }
#pragma unroll
        for (int c = 0; c < C; c++) ps[slot][node][c] = acc[c];
        __syncthreads();
        if (tid < 128) {
            const int n = tid >> 3, c = tid & 7;
            float s = 0.0f;
#pragma unroll
            for (int ss = 0; ss < 16; ss++) s += ps[ss][n][c];
            g_node[(size_t)(n0 + n) * C + c] = s;   // coalesced
        }
        if (bx == 0) {                        // zero poisoned output
            for (int i = tid; i < NG * C; i += 256) out[i] = 0.0f;
        }
    }

    // ============ histogram tasks (blocks 128..591), pre-barrier ============
    unsigned long long hh0[MAXRND], hh1[MAXRND];
    int nheld = 0;
    if (bx >= NA) {
        const int bi = bx - NA;               // 0..463
        const int ntask = nseg_s * 8;         // <= 1024
#pragma unroll
        for (int rnd = 0; rnd < MAXRND; rnd++) {
            const int t = bi + rnd * NBB;
            if (t < ntask) {
                const int mg  = t & 7;
                const int seg = t >> 3;
                const int m     = (mg * 8 + wid) * 32 + lane;
                const int start = s_start[seg];
                const int len   = s_len[seg];
                const float* pd = dist + (size_t)start * NN + m;

                unsigned long long h0 = 0ull, h1 = 0ull; // 12 x 10-bit fields
#pragma unroll
                for (int half = 0; half < 2; half++) {
                    float fd[16];
#pragma unroll
                    for (int i = 0; i < 16; i++) {   // 16 independent LDGs
                        const int r = half * 16 + i;
                        fd[i] = (r < len) ? __ldg(pd + (size_t)r * NN) : -1.0f;
                    }
#pragma unroll
                    for (int i = 0; i < 16; i++) {
                        int di = (int)fd[i] + 1;     // -1..10 -> 0..11 exact
                        di = max(0, min(11, di));
                        const bool hi = di >= 6;
                        const unsigned long long inc =
                            1ull << (10 * (hi ? di - 6 : di));
                        if (hi) h1 += inc; else h0 += inc;
                    }
                }
                hh0[rnd] = h0; hh1[rnd] = h1;
                nheld = rnd + 1;
            }
        }
    }

    // ======================= global barrier =======================
    __syncthreads();
    if (tid == 0) {
        __threadfence();                      // publish g_node / out zeros
        atomicAdd(&d_bar0, 1);
        while (*(volatile int*)&d_bar0 < NB) { __nanosleep(64); }
    }
    __syncthreads();
    __threadfence();                          // acquire g_node

    // ======================= emit held histograms =======================
    if (bx >= NA) {
        const int bi = bx - NA;
        for (int rnd = 0; rnd < nheld; rnd++) {
            const int t   = bi + rnd * NBB;
            const int mg  = t & 7;
            const int seg = t >> 3;
            const int m   = (mg * 8 + wid) * 32 + lane;
            const int gb  = s_graph[seg];
            const unsigned long long h0 = hh0[rnd], h1 = hh1[rnd];

            float p[C];
#pragma unroll
            for (int c = 0; c < C; c++) p[c] = 0.0f;
#pragma unroll
            for (int d = 1; d < 12; d++) {    // bucket 0 (dist=-1) -> 0
                const unsigned int cnt = (unsigned int)
                    ((d < 6 ? (h0 >> (10 * d)) : (h1 >> (10 * (d - 6)))) & 1023u);
                const float fc = (float)cnt;
#pragma unroll
                for (int c = 0; c < C; c++)
                    p[c] = fmaf(fc, er_s[d - 1][c], p[c]);
            }
            {
                const float4* gp = reinterpret_cast<const float4*>(g_node + (size_t)m * C);
                const float4 ga = gp[0];
                const float4 gb4 = gp[1];
                p[0] *= ga.x;  p[1] *= ga.y;  p[2] *= ga.z;  p[3] *= ga.w;
                p[4] *= gb4.x; p[5] *= gb4.y; p[6] *= gb4.z; p[7] *= gb4.w;
            }
#pragma unroll
            for (int off = 16; off; off >>= 1)
#pragma unroll
                for (int c = 0; c < C; c++)
                    p[c] += __shfl_xor_sync(0xffffffffu, p[c], off);

            if (lane == 0) {
#pragma unroll
                for (int c = 0; c < C; c++) bp[wid][c] = p[c];
            }
            __syncthreads();
            if (tid < C) {
                float s = 0.0f;
#pragma unroll
                for (int ww = 0; ww < 8; ww++) s += bp[ww][tid];
                atomicAdd(out + gb * C + tid, s);
            }
            __syncthreads();                  // bp reused next round
        }
    }

    // ======================= stateless reset =======================
    if (tid == 0) {
        const int o = atomicAdd(&d_bar1, 1);
        if (o == NB - 1) {                    // last block restores zeros
            d_bar1 = 0;
            __threadfence();
            d_bar0 = 0;
        }
    }
}

// ---------------------------------------------------------------------------
extern "C" void kernel_launch(void* const* d_in, const int* in_sizes, int n_in,
                              void* d_out, int out_size)
{
    const float* x    = (const float*)d_in[0];
    const float* dist = (const float*)d_in[1];
    const int*   bv   = (const int*)d_in[2];
    const float* fw1  = (const float*)d_in[3];
    const float* fb1  = (const float*)d_in[4];
    const float* fw2  = (const float*)d_in[5];
    const float* fb2  = (const float*)d_in[6];
    const float* rw1  = (const float*)d_in[7];
    const float* rb1  = (const float*)d_in[8];
    const float* rw2  = (const float*)d_in[9];
    const float* rb2  = (const float*)d_in[10];
    float* out = (float*)d_out;

    tgnan_fused<<<NB, 256>>>(x, bv, fw1, fb1, fw2, fb2, rw1, rb1, rw2, rb2,
                             dist, out);
}

// round 15
// speedup vs baseline: 2.2838x; 1.0083x over previous
#include <cuda_runtime.h>

#define NN 2048
#define FEAT 64
#define HID 16
#define C 8
#define NG 64
#define NB 592         // persistent blocks; 4/SM (64 regs), all wave-1 resident
#define NA 64          // phase-A blocks (g_node, 32 nodes each)
#define NTASK (NG * 8) // 512 hist tasks: (graph, m-stripe); one per hist block

// device globals (allocation-free rule); barrier counters restored to 0 by
// the last block of every call -> kernel is stateless/graph-replayable.
__device__ __align__(16) float g_node[NN * C];
__device__ int d_bar0;
__device__ int d_bar1;

// ---------------------------------------------------------------------------
// Single fused persistent kernel, 592 x 256, one launch.
//  * blocks 0..63  (phase A): g_node MLP, 32 nodes/block; block 0 zeroes out.
//  * blocks 64..575 (hist):   local e-table + graph boundary scan (L2-hot),
//    then ONE task = (graph, 256-column stripe): whole-graph histogram in
//    2x u64 (12 buckets x 10-bit). Runs concurrently with phase A.
//  * global barrier (g_node ready) -> single emit per task -> reset.
// ---------------------------------------------------------------------------
__global__ void __launch_bounds__(256, 4) tgnan_fused(
    const float* __restrict__ x,
    const int*   __restrict__ batch,
    const float* __restrict__ w1, const float* __restrict__ b1,
    const float* __restrict__ w2, const float* __restrict__ b2,
    const float* __restrict__ rw1, const float* __restrict__ rb1,
    const float* __restrict__ rw2, const float* __restrict__ rb2,
    const float* __restrict__ dist,
    float* __restrict__ out)
{
    __shared__ float x_s[32 * 65];            // phase A
    __shared__ float ps[8][32][C];            // phase A partials
    __shared__ float er_s[11][C];             // hist: e-table
    __shared__ float bp[8][C];                // hist: per-warp emit partials
    __shared__ int bstart[NG + 1];            // hist: graph start rows
    __shared__ int len_s[NG];                 // hist: graph lengths

    const int tid  = threadIdx.x;
    const int wid  = tid >> 5;
    const int lane = tid & 31;
    const int bx   = blockIdx.x;

    int glen = 0, gb = 0, m = 0;              // hist task state
    unsigned long long h0 = 0ull, h1 = 0ull;  // 12 buckets x 10-bit fields

    if (bx < NA) {
        // ======================= Phase A =======================
        const int n0 = bx * 32;
        for (int i = tid; i < 32 * 64; i += 256) {
            const int r = i >> 6, cc = i & 63;
            x_s[r * 65 + cc] = __ldg(x + (size_t)(n0 + r) * FEAT + cc);
        }
        __syncthreads();

        float acc[C];
#pragma unroll
        for (int c = 0; c < C; c++) acc[c] = 0.0f;
#pragma unroll
        for (int k = 0; k < 8; k++) {
            const int f = wid * 8 + k;            // warp-uniform feature
            const float xv = x_s[lane * 65 + f];  // conflict-free
            const float4* b2p = reinterpret_cast<const float4*>(b2 + f * C);
            const float4 b2a = __ldg(b2p);
            const float4 b2b = __ldg(b2p + 1);
            acc[0] += b2a.x; acc[1] += b2a.y; acc[2] += b2a.z; acc[3] += b2a.w;
            acc[4] += b2b.x; acc[5] += b2b.y; acc[6] += b2b.z; acc[7] += b2b.w;
#pragma unroll
            for (int h = 0; h < HID; h++) {
                const float hv = fmaxf(fmaf(xv, __ldg(w1 + f * HID + h),
                                            __ldg(b1 + f * HID + h)), 0.0f);
                const float4* wp = reinterpret_cast<const float4*>(w2 + (size_t)(f * HID + h) * C);
                const float4 wa = __ldg(wp);      // warp-uniform 32B
                const float4 wb = __ldg(wp + 1);
                acc[0] = fmaf(hv, wa.x, acc[0]);
                acc[1] = fmaf(hv, wa.y, acc[1]);
                acc[2] = fmaf(hv, wa.z, acc[2]);
                acc[3] = fmaf(hv, wa.w, acc[3]);
                acc[4] = fmaf(hv, wb.x, acc[4]);
                acc[5] = fmaf(hv, wb.y, acc[5]);
                acc[6] = fmaf(hv, wb.z, acc[6]);
                acc[7] = fmaf(hv, wb.w, acc[7]);
            }
        }
#pragma unroll
        for (int c = 0; c < C; c++) ps[wid][lane][c] = acc[c];
        __syncthreads();
        {
            const int n = tid >> 3, c = tid & 7;
            float s = 0.0f;
#pragma unroll
            for (int ww = 0; ww < 8; ww++) s += ps[ww][n][c];
            g_node[(size_t)(n0 + n) * C + c] = s;   // coalesced
        }
        if (bx == 0) {                        // zero poisoned output
            for (int i = tid; i < NG * C; i += 256) out[i] = 0.0f;
        }
    } else {
        // ======================= Hist blocks =======================
        // local e-table: rho MLP at dist = 0..10 (dist=-1 contributes 0)
        if (tid < 11) {
            const float dd = (float)tid;
            float a2[C];
#pragma unroll
            for (int c = 0; c < C; c++) a2[c] = rb2[c];
#pragma unroll
            for (int h = 0; h < HID; h++) {
                const float hv = fmaxf(fmaf(dd, rw1[h], rb1[h]), 0.0f);
#pragma unroll
                for (int c = 0; c < C; c++)
                    a2[c] = fmaf(hv, rw2[h * C + c], a2[c]);
            }
#pragma unroll
            for (int c = 0; c < C; c++) er_s[tid][c] = a2[c];
        }
        // graph boundary scan (L2-hot batch)
        if (tid <= NG) bstart[tid] = (tid == NG) ? NN : -1;
        __syncthreads();
        for (int r = tid; r < NN; r += 256) {
            const int b    = __ldg(batch + r);
            const int prev = (r == 0) ? -1 : __ldg(batch + r - 1);
            if (b != prev) bstart[b] = r;     // unique writer per graph
        }
        __syncthreads();
        if (tid < NG) {
            const int s0 = bstart[tid];
            int len = 0;
            if (s0 >= 0) {
                int e = NN;
                for (int g2 = tid + 1; g2 <= NG; g2++)
                    if (bstart[g2] >= 0) { e = bstart[g2]; break; }
                len = e - s0;
            }
            len_s[tid] = len;
        }
        __syncthreads();

        const int bi = bx - NA;               // 0..527
        if (bi < NTASK) {
            gb = bi >> 3;                     // graph
            const int mg = bi & 7;            // m-stripe
            m = (mg * 8 + wid) * 32 + lane;
            const int gstart = max(0, bstart[gb]);
            glen = len_s[gb];
            const float* pd = dist + (size_t)gstart * NN + m;

            for (int r0 = 0; r0 < glen; r0 += 16) {
                float fd[16];
#pragma unroll
                for (int i = 0; i < 16; i++) {    // 16 independent LDGs
                    const int r = r0 + i;
                    fd[i] = (r < glen) ? __ldg(pd + (size_t)r * NN) : -1.0f;
                }
#pragma unroll
                for (int i = 0; i < 16; i++) {
                    int di = (int)fd[i] + 1;      // -1..10 -> 0..11 exact
                    di = min(11, di);             // shift-safety
                    const bool hi = di >= 6;
                    const unsigned long long inc =
                        1ull << (10 * (hi ? di - 6 : di));
                    if (hi) h1 += inc; else h0 += inc;
                }
            }
        }
    }

    // ======================= global barrier =======================
    __syncthreads();
    if (tid == 0) {
        __threadfence();                      // publish g_node / out zeros
        atomicAdd(&d_bar0, 1);
        while (*(volatile int*)&d_bar0 < NB) { __nanosleep(64); }
    }
    __syncthreads();
    __threadfence();                          // acquire g_node

    // ======================= single emit per task =======================
    if (bx >= NA && (bx - NA) < NTASK) {
        float p[C];
#pragma unroll
        for (int c = 0; c < C; c++) p[c] = 0.0f;
#pragma unroll
        for (int d = 1; d < 12; d++) {        // bucket 0 (dist=-1) -> 0
            const unsigned int cnt = (unsigned int)
                ((d < 6 ? (h0 >> (10 * d)) : (h1 >> (10 * (d - 6)))) & 1023u);
            const float fc = (float)cnt;
#pragma unroll
            for (int c = 0; c < C; c++)
                p[c] = fmaf(fc, er_s[d - 1][c], p[c]);
        }
        {
            const float4* gp = reinterpret_cast<const float4*>(g_node + (size_t)m * C);
            const float4 ga = gp[0];
            const float4 gb4 = gp[1];
            p[0] *= ga.x;  p[1] *= ga.y;  p[2] *= ga.z;  p[3] *= ga.w;
            p[4] *= gb4.x; p[5] *= gb4.y; p[6] *= gb4.z; p[7] *= gb4.w;
        }
#pragma unroll
        for (int off = 16; off; off >>= 1)
#pragma unroll
            for (int c = 0; c < C; c++)
                p[c] += __shfl_xor_sync(0xffffffffu, p[c], off);

        if (lane == 0) {
#pragma unroll
            for (int c = 0; c < C; c++) bp[wid][c] = p[c];
        }
        __syncthreads();
        if (tid < C) {
            float s = 0.0f;
#pragma unroll
            for (int ww = 0; ww < 8; ww++) s += bp[ww][tid];
            atomicAdd(out + gb * C + tid, s);
        }
    }

    // ======================= stateless reset =======================
    if (tid == 0) {
        const int o = atomicAdd(&d_bar1, 1);
        if (o == NB - 1) {                    // last block restores zeros
            d_bar1 = 0;
            __threadfence();
            d_bar0 = 0;
        }
    }
}

// ---------------------------------------------------------------------------
extern "C" void kernel_launch(void* const* d_in, const int* in_sizes, int n_in,
                              void* d_out, int out_size)
{
    const float* x    = (const float*)d_in[0];
    const float* dist = (const float*)d_in[1];
    const int*   bv   = (const int*)d_in[2];
    const float* fw1  = (const float*)d_in[3];
    const float* fb1  = (const float*)d_in[4];
    const float* fw2  = (const float*)d_in[5];
    const float* fb2  = (const float*)d_in[6];
    const float* rw1  = (const float*)d_in[7];
    const float* rb1  = (const float*)d_in[8];
    const float* rw2  = (const float*)d_in[9];
    const float* rb2  = (const float*)d_in[10];
    float* out = (float*)d_out;

    tgnan_fused<<<NB, 256>>>(x, bv, fw1, fb1, fw2, fb2, rw1, rb1, rw2, rb2,
                             dist, out);
}

// round 16
// speedup vs baseline: 2.3108x; 1.0118x over previous
#include <cuda_runtime.h>

#define NN 2048
#define FEAT 64
#define HID 16
#define C 8
#define NG 64
#define NA 64             // phase-A blocks (32 nodes each)
#define NTASK 512         // hist tasks: (graph, 256-col stripe)
#define NB (NA + NTASK)   // 576 blocks, 4/SM resident (not required for safety)

// device globals (allocation-free rule); counters restored to 0 by the last
// finishing block of every call -> kernel is stateless/graph-replayable.
__device__ __align__(16) float g_node[NN * C];
__device__ int d_stripe[8];   // per-stripe ready count; target = 9
__device__ int d_fin;         // completion counter for stateless reset

// ---------------------------------------------------------------------------
// Single fused persistent kernel, 576 x 256, one launch, NO global barrier.
//  * blocks 0..63 (A): g_node MLP (32 nodes, warp-uniform weights). Block 0
//    zeroes out first (+1 on every stripe flag). After writing its 32 rows,
//    each A-block bumps d_stripe[bx>>3]. A-blocks never wait.
//  * blocks 64..575 (hist): local e-table + boundary scan + whole-graph
//    column-stripe histogram (2x u64, 12x10-bit) -- all dependency-free.
//    Then poll ONLY d_stripe[own stripe] (==9), emit once, done.
//  * last of 576 blocks resets flags (stateless).
// ---------------------------------------------------------------------------
__global__ void __launch_bounds__(256, 4) tgnan_fused(
    const float* __restrict__ x,
    const int*   __restrict__ batch,
    const float* __restrict__ w1, const float* __restrict__ b1,
    const float* __restrict__ w2, const float* __restrict__ b2,
    const float* __restrict__ rw1, const float* __restrict__ rb1,
    const float* __restrict__ rw2, const float* __restrict__ rb2,
    const float* __restrict__ dist,
    float* __restrict__ out)
{
    __shared__ float x_s[32 * 65];            // A: 32 nodes x 64 feats (pad)
    __shared__ float ps[8][32][C];            // A: per-warp partials
    __shared__ float er_s[11][C];             // hist: e-table
    __shared__ float bp[8][C];                // hist: emit partials
    __shared__ int bstart[NG + 1];            // hist: graph start rows
    __shared__ int len_s[NG];                 // hist: graph lengths

    const int tid  = threadIdx.x;
    const int wid  = tid >> 5;
    const int lane = tid & 31;
    const int bx   = blockIdx.x;

    if (bx < NA) {
        // ======================= Phase A (wait-free) =======================
        if (bx == 0) {
            for (int i = tid; i < NG * C; i += 256) out[i] = 0.0f;
            __syncthreads();
            __threadfence();
            if (tid < 8) atomicAdd(&d_stripe[tid], 1);   // publish zeroed out
        }
        const int n0 = bx * 32;
        for (int i = tid; i < 32 * 64; i += 256) {
            const int r = i >> 6, cc = i & 63;
            x_s[r * 65 + cc] = __ldg(x + (size_t)(n0 + r) * FEAT + cc);
        }
        __syncthreads();

        float acc[C];
#pragma unroll
        for (int c = 0; c < C; c++) acc[c] = 0.0f;
#pragma unroll
        for (int k = 0; k < 8; k++) {
            const int f = wid * 8 + k;            // warp-uniform feature
            const float xv = x_s[lane * 65 + f];  // conflict-free
            const float4* b2p = reinterpret_cast<const float4*>(b2 + f * C);
            const float4 b2a = __ldg(b2p);
            const float4 b2b = __ldg(b2p + 1);
            acc[0] += b2a.x; acc[1] += b2a.y; acc[2] += b2a.z; acc[3] += b2a.w;
            acc[4] += b2b.x; acc[5] += b2b.y; acc[6] += b2b.z; acc[7] += b2b.w;
#pragma unroll
            for (int h = 0; h < HID; h++) {
                const float hv = fmaxf(fmaf(xv, __ldg(w1 + f * HID + h),
                                            __ldg(b1 + f * HID + h)), 0.0f);
                const float4* wp = reinterpret_cast<const float4*>(w2 + (size_t)(f * HID + h) * C);
                const float4 wa = __ldg(wp);      // warp-uniform 32B
                const float4 wb = __ldg(wp + 1);
                acc[0] = fmaf(hv, wa.x, acc[0]);
                acc[1] = fmaf(hv, wa.y, acc[1]);
                acc[2] = fmaf(hv, wa.z, acc[2]);
                acc[3] = fmaf(hv, wa.w, acc[3]);
                acc[4] = fmaf(hv, wb.x, acc[4]);
                acc[5] = fmaf(hv, wb.y, acc[5]);
                acc[6] = fmaf(hv, wb.z, acc[6]);
                acc[7] = fmaf(hv, wb.w, acc[7]);
            }
        }
#pragma unroll
        for (int c = 0; c < C; c++) ps[wid][lane][c] = acc[c];
        __syncthreads();
        {
            const int n = tid >> 3, c = tid & 7;
            float s = 0.0f;
#pragma unroll
            for (int ww = 0; ww < 8; ww++) s += ps[ww][n][c];
            g_node[(size_t)(n0 + n) * C + c] = s;   // coalesced
        }
        __syncthreads();                      // all 32 rows written block-wide
        __threadfence();                      // publish g_node slice
        if (tid == 0) atomicAdd(&d_stripe[bx >> 3], 1);
    } else {
        // ======================= Hist blocks =======================
        // local e-table: rho MLP at dist = 0..10 (dist=-1 contributes 0)
        if (tid < 11) {
            const float dd = (float)tid;
            float a2[C];
#pragma unroll
            for (int c = 0; c < C; c++) a2[c] = rb2[c];
#pragma unroll
            for (int h = 0; h < HID; h++) {
                const float hv = fmaxf(fmaf(dd, rw1[h], rb1[h]), 0.0f);
#pragma unroll
                for (int c = 0; c < C; c++)
                    a2[c] = fmaf(hv, rw2[h * C + c], a2[c]);
            }
#pragma unroll
            for (int c = 0; c < C; c++) er_s[tid][c] = a2[c];
        }
        // graph boundary scan (L2-hot batch)
        if (tid <= NG) bstart[tid] = (tid == NG) ? NN : -1;
        __syncthreads();
        for (int r = tid; r < NN; r += 256) {
            const int b    = __ldg(batch + r);
            const int prev = (r == 0) ? -1 : __ldg(batch + r - 1);
            if (b != prev) bstart[b] = r;     // unique writer per graph
        }
        __syncthreads();
        if (tid < NG) {
            const int s0 = bstart[tid];
            int len = 0;
            if (s0 >= 0) {
                int e = NN;
                for (int g2 = tid + 1; g2 <= NG; g2++)
                    if (bstart[g2] >= 0) { e = bstart[g2]; break; }
                len = e - s0;
            }
            len_s[tid] = len;
        }
        __syncthreads();

        const int bi = bx - NA;               // 0..511
        const int gb = bi >> 3;               // graph
        const int mg = bi & 7;                // column stripe
        const int m  = (mg * 8 + wid) * 32 + lane;
        const int gstart = max(0, bstart[gb]);
        const int glen   = len_s[gb];
        const float* pd  = dist + (size_t)gstart * NN + m;

        unsigned long long h0 = 0ull, h1 = 0ull; // 12 buckets x 10-bit fields
        for (int r0 = 0; r0 < glen; r0 += 16) {
            float fd[16];
#pragma unroll
            for (int i = 0; i < 16; i++) {    // 16 independent LDGs
                const int r = r0 + i;
                fd[i] = (r < glen) ? __ldg(pd + (size_t)r * NN) : -1.0f;
            }
#pragma unroll
            for (int i = 0; i < 16; i++) {
                int di = (int)fd[i] + 1;      // -1..10 -> 0..11 exact
                di = min(11, di);             // shift-safety
                const bool hi = di >= 6;
                const unsigned long long inc =
                    1ull << (10 * (hi ? di - 6 : di));
                if (hi) h1 += inc; else h0 += inc;
            }
        }

        // ---- wait ONLY for this stripe's g_node slice (+ zeroed out) ----
        if (tid == 0) {
            int ns = 32;
            while (*(volatile int*)&d_stripe[mg] < 9) {
                __nanosleep(ns);
                ns = min(ns * 2, 512);        // backoff: cap poll storm
            }
        }
        __syncthreads();
        __threadfence();                      // acquire g_node / out zeros

        // ======================= emit =======================
        float p[C];
#pragma unroll
        for (int c = 0; c < C; c++) p[c] = 0.0f;
#pragma unroll
        for (int d = 1; d < 12; d++) {        // bucket 0 (dist=-1) -> 0
            const unsigned int cnt = (unsigned int)
                ((d < 6 ? (h0 >> (10 * d)) : (h1 >> (10 * (d - 6)))) & 1023u);
            const float fc = (float)cnt;
#pragma unroll
            for (int c = 0; c < C; c++)
                p[c] = fmaf(fc, er_s[d - 1][c], p[c]);
        }
        {
            const float4* gp = reinterpret_cast<const float4*>(g_node + (size_t)m * C);
            const float4 ga = gp[0];
            const float4 gb4 = gp[1];
            p[0] *= ga.x;  p[1] *= ga.y;  p[2] *= ga.z;  p[3] *= ga.w;
            p[4] *= gb4.x; p[5] *= gb4.y; p[6] *= gb4.z; p[7] *= gb4.w;
        }
#pragma unroll
        for (int off = 16; off; off >>= 1)
#pragma unroll
            for (int c = 0; c < C; c++)
                p[c] += __shfl_xor_sync(0xffffffffu, p[c], off);

        if (lane == 0) {
#pragma unroll
            for (int c = 0; c < C; c++) bp[wid][c] = p[c];
        }
        __syncthreads();
        if (tid < C) {
            float s = 0.0f;
#pragma unroll
            for (int ww = 0; ww < 8; ww++) s += bp[ww][tid];
            atomicAdd(out + gb * C + tid, s);
        }
    }

    // ======================= stateless reset =======================
    __syncthreads();
    if (tid == 0) {
        const int o = atomicAdd(&d_fin, 1);
        if (o == NB - 1) {                    // last block restores zeros
#pragma unroll
            for (int s = 0; s < 8; s++) d_stripe[s] = 0;
            __threadfence();
            d_fin = 0;
        }
    }
}

// ---------------------------------------------------------------------------
extern "C" void kernel_launch(void* const* d_in, const int* in_sizes, int n_in,
                              void* d_out, int out_size)
{
    const float* x    = (const float*)d_in[0];
    const float* dist = (const float*)d_in[1];
    const int*   bv   = (const int*)d_in[2];
    const float* fw1  = (const float*)d_in[3];
    const float* fb1  = (const float*)d_in[4];
    const float* fw2  = (const float*)d_in[5];
    const float* fb2  = (const float*)d_in[6];
    const float* rw1  = (const float*)d_in[7];
    const float* rb1  = (const float*)d_in[8];
    const float* rw2  = (const float*)d_in[9];
    const float* rb2  = (const float*)d_in[10];
    float* out = (float*)d_out;

    tgnan_fused<<<NB, 256>>>(x, bv, fw1, fb1, fw2, fb2, rw1, rb1, rw2, rb2,
                             dist, out);
}